// round 14
// baseline (speedup 1.0000x reference)
#include <cuda_runtime.h>

#define S_SRC 16384
#define T_GRID 4096
#define NHBR 8
#define BATCH 4
#define EDIM 16
#define GBINS 64
#define NBINS (GBINS * GBINS)
#define CELL (1.0f / 64.0f)
#define BCAP 32

// Scratch (static device globals — no allocation). g_cnt zero-initialized at
// load; re-zeroed each launch by interp_kernel block 0 for graph replays.
__device__ float  g_xg[BATCH * T_GRID * EDIM];
__device__ int    g_cnt[NBINS];
__device__ float2 g_bxy[NBINS * BCAP];
__device__ int    g_bidx[NBINS * BCAP];

__device__ __forceinline__ int clampb(int v) { return min(max(v, 0), GBINS - 1); }

// ---------------------------------------------------------------------------
// Binning: direct scatter into fixed-capacity bins (Poisson(4); BCAP=32
// overflow probability ~4e-9). Bin-internal order nondeterministic, but
// top-k uses a total order on (d2,idx) keys -> deterministic output.
// ---------------------------------------------------------------------------
__global__ __launch_bounds__(256) void bins_build(const float* __restrict__ cs) {
  const int i = blockIdx.x * 256 + threadIdx.x;
  const float x = cs[i];
  const float y = cs[S_SRC + i];
  const int b = clampb((int)(x * (float)GBINS)) * GBINS +
                clampb((int)(y * (float)GBINS));
  const int p = atomicAdd(&g_cnt[b], 1);
  if (p < BCAP) {
    g_bxy[b * BCAP + p] = make_float2(x, y);
    g_bidx[b * BCAP + p] = i;
  }
}

// ---------------------------------------------------------------------------
// kNN helpers (warp-uniform).
// Key = (f32bits(d2)<<32)|idx reproduces lax.top_k(-d2) order + tie-break.
// ---------------------------------------------------------------------------
__device__ __forceinline__ void insert_key(unsigned long long key,
                                           unsigned long long best[8],
                                           float& worst) {
  if (key < best[7]) {
    best[7] = key;
#pragma unroll
    for (int k = 7; k > 0; k--) {
      unsigned long long lo = (best[k] < best[k - 1]) ? best[k] : best[k - 1];
      unsigned long long hi = (best[k] < best[k - 1]) ? best[k - 1] : best[k];
      best[k - 1] = lo;
      best[k] = hi;
    }
    worst = __uint_as_float((unsigned)(best[7] >> 32));
  }
}

__device__ __forceinline__ void try_candidate(int slot, float gx, float gy,
                                              unsigned long long best[8],
                                              float& worst) {
  const float2 p = g_bxy[slot];
  const float dx = gx - p.x;
  const float dy = gy - p.y;
  const float d2 = fmaf(dy, dy, dx * dx);
  if (d2 <= worst) {
    unsigned long long key =
        ((unsigned long long)__float_as_uint(d2) << 32) | (unsigned)g_bidx[slot];
    insert_key(key, best, worst);
  }
}

__device__ __forceinline__ unsigned long long merge8_32(
    const unsigned long long best[8], int lane, unsigned long long& mine) {
  unsigned long long cand = best[0];
  int p = 0;
  unsigned long long m = 0;
#pragma unroll
  for (int k = 0; k < 8; k++) {
    m = cand;
#pragma unroll
    for (int off = 16; off > 0; off >>= 1) {
      unsigned long long o = __shfl_xor_sync(0xffffffffu, m, off);
      m = (o < m) ? o : m;
    }
    if (lane == k) mine = m;
    if (cand == m) {
      p++;
      cand = (p < 8) ? best[p] : 0xFFFFFFFFFFFFFFFFULL;
    }
  }
  return m;
}

// ---------------------------------------------------------------------------
// Fused kNN + weights + xg: ONE WARP per grid point, fully autonomous after
// the merge (neighbor indices in registers via shfl; no g_idx round-trip,
// no barrier — the kernel boundary after bins_build orders producers).
// wx phase: lane = n*4 + h2 (conflict-free smem tables, verified in R12/R13).
// Block = 256 threads = 8 points. Grid = 512.
// ---------------------------------------------------------------------------
__global__ __launch_bounds__(256) void knnwx_kernel(
    const float* __restrict__ x,
    const float* __restrict__ cs, const float* __restrict__ cg,
    const float* __restrict__ w1, const float* __restrict__ b1,
    const float* __restrict__ w2, const float* __restrict__ b2,
    const float* __restrict__ lng, const float* __restrict__ lnb,
    const float* __restrict__ kw, const float* __restrict__ kb) {
  __shared__ float sW1[128];
  __shared__ float sB1[64];
  __shared__ float4 sW2p[520];     // 4 groups x (16j * 8q) + pad 2/group
  __shared__ float sKWt[8 * 264];  // [j][n(33-stride)][d] conflict-free
  __shared__ float sB2[32], sLNG[32], sLNB[32], sKB[8];

  const int tid = threadIdx.x;
  // Weight tables (loads issue first; complete under the knn phase).
  if (tid < 128) sW1[tid] = w1[tid];
  if (tid < 64) sB1[tid] = b1[tid];
  for (int i = tid; i < 512; i += 256) {
    const int j = i >> 3, q = i & 7;
    sW2p[(j >> 4) * 130 + (j & 15) * 8 + q] = ((const float4*)w2)[i];
  }
  for (int i = tid; i < 2048; i += 256) {
    const int row = i >> 3, j = i & 7;
    sKWt[j * 264 + (row >> 5) * 33 + (row & 31)] = kw[i];
  }
  if (tid < 32) {
    sB2[tid] = b2[tid];
    sLNG[tid] = lng[tid];
    sLNB[tid] = lnb[tid];
  }
  if (tid < 8) sKB[tid] = kb[tid];

  const int t = blockIdx.x * 8 + (tid >> 5);
  const int lane = tid & 31;
  const int n = lane >> 2;   // neighbor 0..7
  const int h2 = lane & 3;   // hidden quarter 0..3

  // ---- kNN (warp-uniform) ----
  const float gx = cg[t];
  const float gy = cg[T_GRID + t];
  const int hbx = clampb((int)(gx * (float)GBINS));
  const int hby = clampb((int)(gy * (float)GBINS));

  unsigned long long best[8];
#pragma unroll
  for (int i = 0; i < 8; i++) best[i] = 0x7F800000FFFFFFFFULL;
  float worst = __int_as_float(0x7F800000);

  int myCnt = 0, myBase = 0;
  if (lane < 9) {
    const int bx = hbx + (lane % 3) - 1;
    const int by = hby + (lane / 3) - 1;
    if (bx >= 0 && bx < GBINS && by >= 0 && by < GBINS) {
      const int bb = bx * GBINS + by;
      myCnt = min(g_cnt[bb], BCAP);
      myBase = bb * BCAP;
    }
  }
#pragma unroll
  for (int i = 0; i < 9; i++) {
    const int cnt = __shfl_sync(0xffffffffu, myCnt, i);
    const int base = __shfl_sync(0xffffffffu, myBase, i);
    for (int c = lane; c < cnt; c += 32)
      try_candidate(base + c, gx, gy, best, worst);
  }

  unsigned long long mine = 0;
  unsigned long long m8 = merge8_32(best, lane, mine);
  float gw = __uint_as_float((unsigned)(m8 >> 32));

  for (int r = 2; r < GBINS; r++) {
    const float dmin = (float)(r - 1) * CELL;
    if (dmin * dmin > gw) break;
    const int nring = 8 * r;
    for (int idx = lane; idx < nring; idx += 32) {
      const int seg = idx / (2 * r);
      const int off = idx - seg * 2 * r;
      int dx, dy;
      if (seg == 0) { dx = -r + off; dy = -r; }
      else if (seg == 1) { dx = -r + 1 + off; dy = r; }
      else if (seg == 2) { dx = -r; dy = -r + 1 + off; }
      else { dx = r; dy = -r + off; }
      const int bx = hbx + dx, by = hby + dy;
      if (bx < 0 || bx >= GBINS || by < 0 || by >= GBINS) continue;
      const int bb = bx * GBINS + by;
      const int cnt = min(g_cnt[bb], BCAP);
      const int base = bb * BCAP;
      for (int c = 0; c < cnt; c++)
        try_candidate(base + c, gx, gy, best, worst);
    }
    m8 = merge8_32(best, lane, mine);
    gw = __uint_as_float((unsigned)(m8 >> 32));
  }
  const int mine_idx = (int)(mine & 0xFFFFFFFFu);  // valid at lanes 0..7

  // ---- weights: PE MLP (quarter j-range per lane) -> LN -> logits ----
  const int si = __shfl_sync(0xffffffffu, mine_idx, n);
  const float r0 = cs[si] - gx;
  const float r1 = cs[S_SRC + si] - gy;

  __syncthreads();  // weight tables ready

  float pe[32];
#pragma unroll
  for (int d = 0; d < 32; d++) pe[d] = (h2 == 0) ? sB2[d] : 0.0f;

  const int jbase = h2 << 4;
  const int gbase4 = h2 * 130;
#pragma unroll 2
  for (int jj = 0; jj < 16; jj++) {
    const int j = jbase + jj;
    float hv = fmaf(r1, sW1[64 + j], fmaf(r0, sW1[j], sB1[j]));
    float z = 0.7978845608028654f * fmaf(0.044715f, hv * hv * hv, hv);
    float g = hv * __fdividef(1.0f, 1.0f + __expf(-2.0f * z));  // gelu_tanh
#pragma unroll
    for (int q = 0; q < 8; q++) {
      float4 wv = sW2p[gbase4 + jj * 8 + q];
      pe[q * 4 + 0] = fmaf(g, wv.x, pe[q * 4 + 0]);
      pe[q * 4 + 1] = fmaf(g, wv.y, pe[q * 4 + 1]);
      pe[q * 4 + 2] = fmaf(g, wv.z, pe[q * 4 + 2]);
      pe[q * 4 + 3] = fmaf(g, wv.w, pe[q * 4 + 3]);
    }
  }
#pragma unroll
  for (int d = 0; d < 32; d++) {
    pe[d] += __shfl_xor_sync(0xffffffffu, pe[d], 1);
    pe[d] += __shfl_xor_sync(0xffffffffu, pe[d], 2);
  }

  float mu = 0.f;
#pragma unroll
  for (int d = 0; d < 32; d++) mu += pe[d];
  mu *= (1.0f / 32.0f);
  float var = 0.f;
#pragma unroll
  for (int d = 0; d < 32; d++) {
    float c = pe[d] - mu;
    var = fmaf(c, c, var);
  }
  var *= (1.0f / 32.0f);
  const float rstd = rsqrtf(var + 1e-5f);
#pragma unroll
  for (int d = 0; d < 32; d++)
    pe[d] = fmaf((pe[d] - mu) * rstd, sLNG[d], sLNB[d]);

  const int j0 = h2 << 1;
  float pl0 = 0.f, pl1 = 0.f;
  const float* kt0 = sKWt + j0 * 264 + n * 33;
  const float* kt1 = kt0 + 264;
#pragma unroll
  for (int d = 0; d < 32; d++) {
    pl0 = fmaf(pe[d], kt0[d], pl0);
    pl1 = fmaf(pe[d], kt1[d], pl1);
  }
#pragma unroll
  for (int off = 4; off <= 16; off <<= 1) {
    pl0 += __shfl_xor_sync(0xffffffffu, pl0, off);
    pl1 += __shfl_xor_sync(0xffffffffu, pl1, off);
  }
  pl0 += sKB[j0];
  pl1 += sKB[j0 + 1];
  const float q0 = __shfl_xor_sync(0xffffffffu, pl0, 1);
  const float q1 = __shfl_xor_sync(0xffffffffu, pl1, 1);
  const float s0 = __shfl_xor_sync(0xffffffffu, pl0, 2);
  const float s1 = __shfl_xor_sync(0xffffffffu, pl1, 2);
  const float u0 = __shfl_xor_sync(0xffffffffu, q0, 2);
  const float u1 = __shfl_xor_sync(0xffffffffu, q1, 2);

  float mx = fmaxf(fmaxf(fmaxf(pl0, pl1), fmaxf(q0, q1)),
                   fmaxf(fmaxf(s0, s1), fmaxf(u0, u1)));
  const float e0 = __expf(pl0 - mx);
  const float e1 = __expf(pl1 - mx);
  const float ssum = e0 + e1 + __expf(q0 - mx) + __expf(q1 - mx) +
                     __expf(s0 - mx) + __expf(s1 - mx) + __expf(u0 - mx) +
                     __expf(u1 - mx);
  const float inv = __fdividef(1.0f, ssum);
  const float e0i = e0 * inv;  // weight for output 2*h2 (uniform over n lanes)
  const float e1i = e1 * inv;  // weight for output 2*h2+1

  // ---- xg gather: lane = (batch, oct); weights+indices via shfl ----
  const int bidx = lane >> 3;  // 0..3
  const int oct = lane & 7;    // 0..7
  float ax = 0.f, ay = 0.f;
  const float* xb = x + (size_t)bidx * S_SRC * EDIM + oct * 2;
#pragma unroll
  for (int nn = 0; nn < NHBR; nn++) {
    const int s = __shfl_sync(0xffffffffu, mine_idx, nn);
    const float wa = __shfl_sync(0xffffffffu, e0i, nn >> 1);
    const float wb = __shfl_sync(0xffffffffu, e1i, nn >> 1);
    const float wgt = (nn & 1) ? wb : wa;
    const float2 v = *(const float2*)(xb + (size_t)s * EDIM);
    ax = fmaf(wgt, v.x, ax);
    ay = fmaf(wgt, v.y, ay);
  }
  *(float2*)(g_xg + (size_t)((bidx << 12) + t) * EDIM + oct * 2) =
      make_float2(ax, ay);
}

// ---------------------------------------------------------------------------
// Gaussian axis window, factorized (identical math to R9).
// ---------------------------------------------------------------------------
__device__ __forceinline__ void fma4(float4& a, float w, const float4 v) {
  a.x = fmaf(w, v.x, a.x);
  a.y = fmaf(w, v.y, a.y);
  a.z = fmaf(w, v.z, a.z);
  a.w = fmaf(w, v.w, a.w);
}

__device__ __forceinline__ void axis_weights(float pos, float rp,
                                             const float* __restrict__ sC,
                                             float w[5]) {
  const float delta = rp - pos;
  const float lnr = -(20.0f / 89.0f) * delta;
  const float r = __expf(lnr);

  float S0 = 0.f, S1 = 0.f, S2 = 0.f, S3 = 0.f, S4 = 0.f;
  float rr = 1.0f;
#pragma unroll
  for (int k = 0; k < 18; k++) {
    S0 = fmaf(sC[k], rr, S0);
    S1 = fmaf(sC[18 + k], rr, S1);
    S2 = fmaf(sC[36 + k], rr, S2);
    S3 = fmaf(sC[54 + k], rr, S3);
    S4 = fmaf(sC[72 + k], rr, S4);
    rr *= r;
  }
  const float q = rr;
  const float q2 = q * q;
  w[0] = S0;
  w[1] = q * S1;
  w[2] = q2 * S2;
  w[3] = q2 * q * S3;
  w[4] = q2 * q2 * S4;

  const int irp = (int)rp;
  if (irp <= 2 || irp >= 62) {
    const float G = __expf(fmaf(-2.0f * delta, delta, 10.0f * delta));
#pragma unroll
    for (int i = 0; i < 5; i++) w[i] *= G;
    if (irp <= 2) {
      const int j0 = (int)ceilf((2.5f - rp) * 17.8f);
      const float K = __expf(-2.0f * pos * pos);
      float rj = G;
#pragma unroll
      for (int i = 0; i < 5; i++) {
        const int jlo = i * 18;
        const int jhi = min(j0, jlo + 18);
        float c = 0.f;
        for (int j = jlo; j < jhi; j++) {
          c += K - sC[j] * rj;
          rj *= r;
        }
        w[i] += c;
      }
    } else {
      const float d64 = 64.0f - pos;
      const float K = __expf(-2.0f * d64 * d64);
      const int jc = (int)floorf((66.5f - rp) * 17.8f) + 1;
      float rjj = G * __expf(lnr * (float)jc);
#pragma unroll
      for (int i = 0; i < 5; i++) {
        const int jlo = max(jc, i * 18);
        const int jhi = (i + 1) * 18;
        float c = 0.f;
        for (int j = jlo; j < jhi; j++) {
          c += K - sC[j] * rjj;
          rjj *= r;
        }
        w[i] += c;
      }
    }
  }
}

// ---------------------------------------------------------------------------
// Gaussian-window resampling (R9 shape, unchanged). FOUR threads per (b, n).
// Zeroes g_cnt (block 0) for the next graph replay.
// ---------------------------------------------------------------------------
__global__ __launch_bounds__(256, 4) void interp_kernel(
    const float* __restrict__ ct, float* __restrict__ out) {
  __shared__ float sC[90];
  {
    const int tt = threadIdx.x;
    if (tt < 90) {
      float off = fmaf((float)tt, -5.0f / 89.0f, 2.5f);
      sC[tt] = __expf(-2.0f * off * off);
    }
    if (blockIdx.x == 0) {
      for (int i = tt; i < NBINS; i += 256) g_cnt[i] = 0;
    }
  }
  __syncthreads();

  const int gid4 = blockIdx.x * 256 + threadIdx.x;  // 131072 = 4*B*N
  const int tgt = gid4 >> 2;
  const int quad = gid4 & 3;
  const int b = tgt >> 13;
  const float2 c2 = ((const float2*)ct)[tgt];
  const float posx = c2.y * 63.0f;
  const float posy = c2.x * 63.0f;
  const float rpx = rintf(posx);
  const float rpy = rintf(posy);

  float wx[5], wy[5];
  axis_weights(posx, rpx, sC, wx);
  axis_weights(posy, rpy, sC, wy);

  const float sx = wx[0] + wx[1] + wx[2] + wx[3] + wx[4];
  const float sy = wy[0] + wy[1] + wy[2] + wy[3] + wy[4];
  const float inv = 1.0f / (sx * sy);

  int ixi[5], iyi[5];
  const int irpx = (int)rpx;
  const int irpy = (int)rpy;
#pragma unroll
  for (int k = 0; k < 5; k++) {
    ixi[k] = min(max(irpx + 2 - k, 0), 63);
    iyi[k] = min(max(irpy + 2 - k, 0), 63);
  }

  float4 acc = {0, 0, 0, 0};
  const float* gbase = g_xg + (size_t)b * (T_GRID * EDIM) + quad * 4;
#pragma unroll
  for (int kx = 0; kx < 5; kx++) {
    const int rowbase = ixi[kx] << 6;
    const float wxk = wx[kx] * inv;
#pragma unroll
    for (int ky = 0; ky < 5; ky++) {
      const float wc = wxk * wy[ky];
      const float4 v =
          *(const float4*)(gbase + (size_t)(rowbase + iyi[ky]) * EDIM);
      fma4(acc, wc, v);
    }
  }
  ((float4*)(out + (size_t)tgt * EDIM))[quad] = acc;
}

// ---------------------------------------------------------------------------
extern "C" void kernel_launch(void* const* d_in, const int* in_sizes, int n_in,
                              void* d_out, int out_size) {
  const float* x   = (const float*)d_in[0];
  const float* cs  = (const float*)d_in[1];
  const float* cg  = (const float*)d_in[2];
  const float* ct  = (const float*)d_in[3];
  const float* w1  = (const float*)d_in[4];
  const float* b1  = (const float*)d_in[5];
  const float* w2  = (const float*)d_in[6];
  const float* b2  = (const float*)d_in[7];
  const float* lng = (const float*)d_in[8];
  const float* lnb = (const float*)d_in[9];
  const float* kw  = (const float*)d_in[10];
  const float* kb  = (const float*)d_in[11];
  float* out = (float*)d_out;

  bins_build<<<64, 256>>>(cs);
  knnwx_kernel<<<512, 256>>>(x, cs, cg, w1, b1, w2, b2, lng, lnb, kw, kb);
  interp_kernel<<<512, 256>>>(ct, out);
}

// round 15
// speedup vs baseline: 1.1405x; 1.1405x over previous
#include <cuda_runtime.h>

#define S_SRC 16384
#define T_GRID 4096
#define NHBR 8
#define BATCH 4
#define EDIM 16
#define GBINS 64
#define NBINS (GBINS * GBINS)
#define CELL (1.0f / 64.0f)
#define BCAP 32

// Scratch (static device globals — no allocation). g_cnt zero-initialized at
// load; re-zeroed each launch by interp_kernel block 0 for graph replays.
__device__ int    g_idx[T_GRID * NHBR];
__device__ float  g_xg[BATCH * T_GRID * EDIM];
__device__ int    g_cnt[NBINS];
__device__ float2 g_bxy[NBINS * BCAP];
__device__ int    g_bidx[NBINS * BCAP];

__device__ __forceinline__ int clampb(int v) { return min(max(v, 0), GBINS - 1); }

// ---------------------------------------------------------------------------
// Binning: direct scatter into fixed-capacity bins (Poisson(4); BCAP=32
// overflow probability ~4e-9). Bin-internal order nondeterministic, but
// top-k uses a total order on (d2,idx) keys -> deterministic output.
// ---------------------------------------------------------------------------
__global__ __launch_bounds__(256) void bins_build(const float* __restrict__ cs) {
  const int i = blockIdx.x * 256 + threadIdx.x;
  const float x = cs[i];
  const float y = cs[S_SRC + i];
  const int b = clampb((int)(x * (float)GBINS)) * GBINS +
                clampb((int)(y * (float)GBINS));
  const int p = atomicAdd(&g_cnt[b], 1);
  if (p < BCAP) {
    g_bxy[b * BCAP + p] = make_float2(x, y);
    g_bidx[b * BCAP + p] = i;
  }
}

// ---------------------------------------------------------------------------
// Exact kNN (k=8): ONE WARP per grid point (R9 verbatim).
// Key = (f32bits(d2)<<32)|idx reproduces lax.top_k(-d2) order + tie-break.
// ---------------------------------------------------------------------------
__device__ __forceinline__ void insert_key(unsigned long long key,
                                           unsigned long long best[8],
                                           float& worst) {
  if (key < best[7]) {
    best[7] = key;
#pragma unroll
    for (int k = 7; k > 0; k--) {
      unsigned long long lo = (best[k] < best[k - 1]) ? best[k] : best[k - 1];
      unsigned long long hi = (best[k] < best[k - 1]) ? best[k - 1] : best[k];
      best[k - 1] = lo;
      best[k] = hi;
    }
    worst = __uint_as_float((unsigned)(best[7] >> 32));
  }
}

__device__ __forceinline__ void try_candidate(int slot, float gx, float gy,
                                              unsigned long long best[8],
                                              float& worst) {
  const float2 p = g_bxy[slot];
  const float dx = gx - p.x;
  const float dy = gy - p.y;
  const float d2 = fmaf(dy, dy, dx * dx);
  if (d2 <= worst) {
    unsigned long long key =
        ((unsigned long long)__float_as_uint(d2) << 32) | (unsigned)g_bidx[slot];
    insert_key(key, best, worst);
  }
}

__device__ __forceinline__ unsigned long long merge8_32(
    const unsigned long long best[8], int lane, unsigned long long& mine) {
  unsigned long long cand = best[0];
  int p = 0;
  unsigned long long m = 0;
#pragma unroll
  for (int k = 0; k < 8; k++) {
    m = cand;
#pragma unroll
    for (int off = 16; off > 0; off >>= 1) {
      unsigned long long o = __shfl_xor_sync(0xffffffffu, m, off);
      m = (o < m) ? o : m;
    }
    if (lane == k) mine = m;
    if (cand == m) {
      p++;
      cand = (p < 8) ? best[p] : 0xFFFFFFFFFFFFFFFFULL;
    }
  }
  return m;
}

__global__ __launch_bounds__(256) void knn_kernel(const float* __restrict__ cg) {
  const int t = (blockIdx.x * 256 + threadIdx.x) >> 5;
  const int lane = threadIdx.x & 31;

  const float gx = cg[t];
  const float gy = cg[T_GRID + t];
  const int hbx = clampb((int)(gx * (float)GBINS));
  const int hby = clampb((int)(gy * (float)GBINS));

  unsigned long long best[8];
#pragma unroll
  for (int i = 0; i < 8; i++) best[i] = 0x7F800000FFFFFFFFULL;
  float worst = __int_as_float(0x7F800000);

  int myCnt = 0, myBase = 0;
  if (lane < 9) {
    const int bx = hbx + (lane % 3) - 1;
    const int by = hby + (lane / 3) - 1;
    if (bx >= 0 && bx < GBINS && by >= 0 && by < GBINS) {
      const int b = bx * GBINS + by;
      myCnt = min(g_cnt[b], BCAP);
      myBase = b * BCAP;
    }
  }

#pragma unroll
  for (int i = 0; i < 9; i++) {
    const int cnt = __shfl_sync(0xffffffffu, myCnt, i);
    const int base = __shfl_sync(0xffffffffu, myBase, i);
    for (int c = lane; c < cnt; c += 32)
      try_candidate(base + c, gx, gy, best, worst);
  }

  unsigned long long mine = 0;
  unsigned long long m8 = merge8_32(best, lane, mine);
  float gw = __uint_as_float((unsigned)(m8 >> 32));

  for (int r = 2; r < GBINS; r++) {
    const float dmin = (float)(r - 1) * CELL;
    if (dmin * dmin > gw) break;
    const int nring = 8 * r;
    for (int idx = lane; idx < nring; idx += 32) {
      const int seg = idx / (2 * r);
      const int off = idx - seg * 2 * r;
      int dx, dy;
      if (seg == 0) { dx = -r + off; dy = -r; }
      else if (seg == 1) { dx = -r + 1 + off; dy = r; }
      else if (seg == 2) { dx = -r; dy = -r + 1 + off; }
      else { dx = r; dy = -r + off; }
      const int bx = hbx + dx, by = hby + dy;
      if (bx < 0 || bx >= GBINS || by < 0 || by >= GBINS) continue;
      const int b = bx * GBINS + by;
      const int cnt = min(g_cnt[b], BCAP);
      const int base = b * BCAP;
      for (int c = 0; c < cnt; c++) try_candidate(base + c, gx, gy, best, worst);
    }
    m8 = merge8_32(best, lane, mine);
    gw = __uint_as_float((unsigned)(m8 >> 32));
  }

  if (lane < 8) g_idx[t * NHBR + lane] = (int)(mine & 0xFFFFFFFFu);
}

// ---------------------------------------------------------------------------
// Weights + xg, j-split 2x (R9 structure): thread = (pt, n, h),
// tid = pt*16 + n*2 + h. ONLY change vs R9: the logits table is transposed
// conflict-free — sKWt[j*266 + n*33 + d] gives bank = 8h + 10k + n + d,
// all 16 active lanes distinct (pt-halves broadcast). R9's layout had
// n-stride 1024B = 8-way LDS conflicts on every logits load.
// Block = 512 threads = 32 points.
// ---------------------------------------------------------------------------
__device__ __forceinline__ void fma4(float4& a, float w, const float4 v) {
  a.x = fmaf(w, v.x, a.x);
  a.y = fmaf(w, v.y, a.y);
  a.z = fmaf(w, v.z, a.z);
  a.w = fmaf(w, v.w, a.w);
}

__global__ __launch_bounds__(512) void weights_xg_kernel(
    const float* __restrict__ x,
    const float* __restrict__ cs, const float* __restrict__ cg,
    const float* __restrict__ w1, const float* __restrict__ b1,
    const float* __restrict__ w2, const float* __restrict__ b2,
    const float* __restrict__ lng, const float* __restrict__ lnb,
    const float* __restrict__ kw, const float* __restrict__ kb) {
  __shared__ float sW1[128];
  __shared__ float sB1[64];
  __shared__ float4 sW2[512];
  __shared__ float sKWt[8 * 266];  // [j(266-stride)][n(33-stride)][d]
  __shared__ float sB2[32], sLNG[32], sLNB[32], sKB[8];
  __shared__ int sIDX[256];
  __shared__ float sWgt[256];

  const int tid = threadIdx.x;
  if (tid < 128) sW1[tid] = w1[tid];
  if (tid < 64) sB1[tid] = b1[tid];
  sW2[tid] = ((const float4*)w2)[tid];
  // k_w: src scalar i = row*8 + j (row = n*32 + d) -> sKWt[j*266 + n*33 + d]
  for (int i = tid; i < 2048; i += 512) {
    const int row = i >> 3, j = i & 7;
    sKWt[j * 266 + (row >> 5) * 33 + (row & 31)] = kw[i];
  }
  if (tid < 32) {
    sB2[tid] = b2[tid];
    sLNG[tid] = lng[tid];
    sLNB[tid] = lnb[tid];
  }
  if (tid < 8) sKB[tid] = kb[tid];

  const int pt = tid >> 4;
  const int n = (tid >> 1) & 7;
  const int h = tid & 1;
  const int t = blockIdx.x * 32 + pt;
  const int si = g_idx[t * NHBR + n];
  if (h == 0) sIDX[pt * 8 + n] = si;
  const float r0 = cs[si] - cg[t];
  const float r1 = cs[S_SRC + si] - cg[T_GRID + t];

  __syncthreads();

  float pe[32];
#pragma unroll
  for (int d = 0; d < 32; d++) pe[d] = h ? 0.0f : sB2[d];

  const int jbase = h << 5;
#pragma unroll 2
  for (int jj = 0; jj < 32; jj++) {
    const int j = jbase + jj;
    float hv = fmaf(r1, sW1[64 + j], fmaf(r0, sW1[j], sB1[j]));
    float z = 0.7978845608028654f * fmaf(0.044715f, hv * hv * hv, hv);
    float g = hv * __fdividef(1.0f, 1.0f + __expf(-2.0f * z));  // gelu_tanh
#pragma unroll
    for (int q = 0; q < 8; q++) {
      float4 wv = sW2[j * 8 + q];
      pe[q * 4 + 0] = fmaf(g, wv.x, pe[q * 4 + 0]);
      pe[q * 4 + 1] = fmaf(g, wv.y, pe[q * 4 + 1]);
      pe[q * 4 + 2] = fmaf(g, wv.z, pe[q * 4 + 2]);
      pe[q * 4 + 3] = fmaf(g, wv.w, pe[q * 4 + 3]);
    }
  }

  // Combine j-halves: partner is lane^1.
#pragma unroll
  for (int d = 0; d < 32; d++)
    pe[d] += __shfl_xor_sync(0xffffffffu, pe[d], 1);

  // LayerNorm (both h compute identically on the combined pe).
  float mu = 0.f;
#pragma unroll
  for (int d = 0; d < 32; d++) mu += pe[d];
  mu *= (1.0f / 32.0f);
  float var = 0.f;
#pragma unroll
  for (int d = 0; d < 32; d++) {
    float c = pe[d] - mu;
    var = fmaf(c, c, var);
  }
  var *= (1.0f / 32.0f);
  const float rstd = rsqrtf(var + 1e-5f);
#pragma unroll
  for (int d = 0; d < 32; d++)
    pe[d] = fmaf((pe[d] - mu) * rstd, sLNG[d], sLNB[d]);  // kf in place

  // Partial logits: this thread covers outputs [h*4, h*4+4). Conflict-free
  // scalar reads from the transposed table.
  float pl[4] = {0.f, 0.f, 0.f, 0.f};
  const float* kt0 = sKWt + (h * 4 + 0) * 266 + n * 33;
  const float* kt1 = kt0 + 266;
  const float* kt2 = kt1 + 266;
  const float* kt3 = kt2 + 266;
#pragma unroll
  for (int d = 0; d < 32; d++) {
    pl[0] = fmaf(pe[d], kt0[d], pl[0]);
    pl[1] = fmaf(pe[d], kt1[d], pl[1]);
    pl[2] = fmaf(pe[d], kt2[d], pl[2]);
    pl[3] = fmaf(pe[d], kt3[d], pl[3]);
  }
  // Reduce over n (tid bits 1..3 -> xor offsets 2,4,8; intra-warp).
#pragma unroll
  for (int k = 0; k < 4; k++) {
    pl[k] += __shfl_xor_sync(0xffffffffu, pl[k], 2);
    pl[k] += __shfl_xor_sync(0xffffffffu, pl[k], 4);
    pl[k] += __shfl_xor_sync(0xffffffffu, pl[k], 8);
  }
  // Fetch the other output half from the h-partner.
  float oth[4];
#pragma unroll
  for (int k = 0; k < 4; k++) oth[k] = __shfl_xor_sync(0xffffffffu, pl[k], 1);

  float lg[8];
#pragma unroll
  for (int k = 0; k < 4; k++) {
    lg[k] = h ? oth[k] : pl[k];
    lg[4 + k] = h ? pl[k] : oth[k];
  }
#pragma unroll
  for (int j = 0; j < 8; j++) lg[j] += sKB[j];

  // Softmax over the 8 outputs, in-register (identical on all 16 pt-threads).
  float mx = lg[0];
#pragma unroll
  for (int j = 1; j < 8; j++) mx = fmaxf(mx, lg[j]);
  float e[8];
  float ssum = 0.f;
#pragma unroll
  for (int j = 0; j < 8; j++) {
    e[j] = __expf(lg[j] - mx);
    ssum += e[j];
  }
  const float inv = __fdividef(1.0f, ssum);
  if (n == 0 && h == 0) {
#pragma unroll
    for (int j = 0; j < 8; j++) sWgt[pt * 8 + j] = e[j] * inv;
  }
  __syncthreads();

  // xg gather: unit = (pt, b); 4 threads per unit, float4 channels each.
  const int u = tid >> 2;
  const int qd = tid & 3;
  const int pt2 = u >> 2;
  const int b = u & 3;
  const int tg = blockIdx.x * 32 + pt2;
  float4 acc = {0, 0, 0, 0};
#pragma unroll
  for (int nn = 0; nn < NHBR; nn++) {
    const int s = sIDX[pt2 * 8 + nn];
    const float w = sWgt[pt2 * 8 + nn];
    const float4 v =
        *(const float4*)(x + (size_t)(b * S_SRC + s) * EDIM + qd * 4);
    fma4(acc, w, v);
  }
  *(float4*)(g_xg + (size_t)((b << 12) + tg) * EDIM + qd * 4) = acc;
}

// ---------------------------------------------------------------------------
// Gaussian axis window, factorized (identical math to R9).
// ---------------------------------------------------------------------------
__device__ __forceinline__ void axis_weights(float pos, float rp,
                                             const float* __restrict__ sC,
                                             float w[5]) {
  const float delta = rp - pos;
  const float lnr = -(20.0f / 89.0f) * delta;
  const float r = __expf(lnr);

  float S0 = 0.f, S1 = 0.f, S2 = 0.f, S3 = 0.f, S4 = 0.f;
  float rr = 1.0f;
#pragma unroll
  for (int k = 0; k < 18; k++) {
    S0 = fmaf(sC[k], rr, S0);
    S1 = fmaf(sC[18 + k], rr, S1);
    S2 = fmaf(sC[36 + k], rr, S2);
    S3 = fmaf(sC[54 + k], rr, S3);
    S4 = fmaf(sC[72 + k], rr, S4);
    rr *= r;
  }
  const float q = rr;
  const float q2 = q * q;
  w[0] = S0;
  w[1] = q * S1;
  w[2] = q2 * S2;
  w[3] = q2 * q * S3;
  w[4] = q2 * q2 * S4;

  const int irp = (int)rp;
  if (irp <= 2 || irp >= 62) {
    const float G = __expf(fmaf(-2.0f * delta, delta, 10.0f * delta));
#pragma unroll
    for (int i = 0; i < 5; i++) w[i] *= G;
    if (irp <= 2) {
      const int j0 = (int)ceilf((2.5f - rp) * 17.8f);
      const float K = __expf(-2.0f * pos * pos);
      float rj = G;
#pragma unroll
      for (int i = 0; i < 5; i++) {
        const int jlo = i * 18;
        const int jhi = min(j0, jlo + 18);
        float c = 0.f;
        for (int j = jlo; j < jhi; j++) {
          c += K - sC[j] * rj;
          rj *= r;
        }
        w[i] += c;
      }
    } else {
      const float d64 = 64.0f - pos;
      const float K = __expf(-2.0f * d64 * d64);
      const int jc = (int)floorf((66.5f - rp) * 17.8f) + 1;
      float rjj = G * __expf(lnr * (float)jc);
#pragma unroll
      for (int i = 0; i < 5; i++) {
        const int jlo = max(jc, i * 18);
        const int jhi = (i + 1) * 18;
        float c = 0.f;
        for (int j = jlo; j < jhi; j++) {
          c += K - sC[j] * rjj;
          rjj *= r;
        }
        w[i] += c;
      }
    }
  }
}

// ---------------------------------------------------------------------------
// Gaussian-window resampling (R9 shape, unchanged). FOUR threads per (b, n).
// Zeroes g_cnt (block 0) for the next graph replay.
// ---------------------------------------------------------------------------
__global__ __launch_bounds__(256, 4) void interp_kernel(
    const float* __restrict__ ct, float* __restrict__ out) {
  __shared__ float sC[90];
  {
    const int tt = threadIdx.x;
    if (tt < 90) {
      float off = fmaf((float)tt, -5.0f / 89.0f, 2.5f);
      sC[tt] = __expf(-2.0f * off * off);
    }
    if (blockIdx.x == 0) {
      for (int i = tt; i < NBINS; i += 256) g_cnt[i] = 0;
    }
  }
  __syncthreads();

  const int gid4 = blockIdx.x * 256 + threadIdx.x;  // 131072 = 4*B*N
  const int tgt = gid4 >> 2;
  const int quad = gid4 & 3;
  const int b = tgt >> 13;
  const float2 c2 = ((const float2*)ct)[tgt];
  const float posx = c2.y * 63.0f;
  const float posy = c2.x * 63.0f;
  const float rpx = rintf(posx);
  const float rpy = rintf(posy);

  float wx[5], wy[5];
  axis_weights(posx, rpx, sC, wx);
  axis_weights(posy, rpy, sC, wy);

  const float sx = wx[0] + wx[1] + wx[2] + wx[3] + wx[4];
  const float sy = wy[0] + wy[1] + wy[2] + wy[3] + wy[4];
  const float inv = 1.0f / (sx * sy);

  int ixi[5], iyi[5];
  const int irpx = (int)rpx;
  const int irpy = (int)rpy;
#pragma unroll
  for (int k = 0; k < 5; k++) {
    ixi[k] = min(max(irpx + 2 - k, 0), 63);
    iyi[k] = min(max(irpy + 2 - k, 0), 63);
  }

  float4 acc = {0, 0, 0, 0};
  const float* gbase = g_xg + (size_t)b * (T_GRID * EDIM) + quad * 4;
#pragma unroll
  for (int kx = 0; kx < 5; kx++) {
    const int rowbase = ixi[kx] << 6;
    const float wxk = wx[kx] * inv;
#pragma unroll
    for (int ky = 0; ky < 5; ky++) {
      const float wc = wxk * wy[ky];
      const float4 v =
          *(const float4*)(gbase + (size_t)(rowbase + iyi[ky]) * EDIM);
      fma4(acc, wc, v);
    }
  }
  ((float4*)(out + (size_t)tgt * EDIM))[quad] = acc;
}

// ---------------------------------------------------------------------------
extern "C" void kernel_launch(void* const* d_in, const int* in_sizes, int n_in,
                              void* d_out, int out_size) {
  const float* x   = (const float*)d_in[0];
  const float* cs  = (const float*)d_in[1];
  const float* cg  = (const float*)d_in[2];
  const float* ct  = (const float*)d_in[3];
  const float* w1  = (const float*)d_in[4];
  const float* b1  = (const float*)d_in[5];
  const float* w2  = (const float*)d_in[6];
  const float* b2  = (const float*)d_in[7];
  const float* lng = (const float*)d_in[8];
  const float* lnb = (const float*)d_in[9];
  const float* kw  = (const float*)d_in[10];
  const float* kb  = (const float*)d_in[11];
  float* out = (float*)d_out;

  bins_build<<<64, 256>>>(cs);
  knn_kernel<<<512, 256>>>(cg);
  weights_xg_kernel<<<128, 512>>>(x, cs, cg, w1, b1, w2, b2, lng, lnb, kw, kb);
  interp_kernel<<<512, 256>>>(ct, out);
}

// round 16
// speedup vs baseline: 1.3099x; 1.1485x over previous
#include <cuda_runtime.h>

#define S_SRC 16384
#define T_GRID 4096
#define NHBR 8
#define BATCH 4
#define EDIM 16
#define GBINS 64
#define NBINS (GBINS * GBINS)
#define CELL (1.0f / 64.0f)
#define BCAP 32

// Scratch (static device globals — no allocation). g_cnt zero-initialized at
// load; re-zeroed each launch by interp_kernel block 0 for graph replays.
__device__ int    g_idx[T_GRID * NHBR];
__device__ float  g_xg[BATCH * T_GRID * EDIM];
__device__ int    g_cnt[NBINS];
__device__ float2 g_bxy[NBINS * BCAP];
__device__ int    g_bidx[NBINS * BCAP];

__device__ __forceinline__ int clampb(int v) { return min(max(v, 0), GBINS - 1); }

// ---------------------------------------------------------------------------
// Binning: direct scatter into fixed-capacity bins (Poisson(4); BCAP=32
// overflow probability ~4e-9). Bin-internal order nondeterministic, but
// top-k uses a total order on (d2,idx) keys -> deterministic output.
// ---------------------------------------------------------------------------
__global__ __launch_bounds__(256) void bins_build(const float* __restrict__ cs) {
  const int i = blockIdx.x * 256 + threadIdx.x;
  const float x = cs[i];
  const float y = cs[S_SRC + i];
  const int b = clampb((int)(x * (float)GBINS)) * GBINS +
                clampb((int)(y * (float)GBINS));
  const int p = atomicAdd(&g_cnt[b], 1);
  if (p < BCAP) {
    g_bxy[b * BCAP + p] = make_float2(x, y);
    g_bidx[b * BCAP + p] = i;
  }
}

// ---------------------------------------------------------------------------
// Exact kNN (k=8): ONE WARP per grid point (R9 verbatim).
// Key = (f32bits(d2)<<32)|idx reproduces lax.top_k(-d2) order + tie-break.
// ---------------------------------------------------------------------------
__device__ __forceinline__ void insert_key(unsigned long long key,
                                           unsigned long long best[8],
                                           float& worst) {
  if (key < best[7]) {
    best[7] = key;
#pragma unroll
    for (int k = 7; k > 0; k--) {
      unsigned long long lo = (best[k] < best[k - 1]) ? best[k] : best[k - 1];
      unsigned long long hi = (best[k] < best[k - 1]) ? best[k - 1] : best[k];
      best[k - 1] = lo;
      best[k] = hi;
    }
    worst = __uint_as_float((unsigned)(best[7] >> 32));
  }
}

__device__ __forceinline__ void try_candidate(int slot, float gx, float gy,
                                              unsigned long long best[8],
                                              float& worst) {
  const float2 p = g_bxy[slot];
  const float dx = gx - p.x;
  const float dy = gy - p.y;
  const float d2 = fmaf(dy, dy, dx * dx);
  if (d2 <= worst) {
    unsigned long long key =
        ((unsigned long long)__float_as_uint(d2) << 32) | (unsigned)g_bidx[slot];
    insert_key(key, best, worst);
  }
}

__device__ __forceinline__ unsigned long long merge8_32(
    const unsigned long long best[8], int lane, unsigned long long& mine) {
  unsigned long long cand = best[0];
  int p = 0;
  unsigned long long m = 0;
#pragma unroll
  for (int k = 0; k < 8; k++) {
    m = cand;
#pragma unroll
    for (int off = 16; off > 0; off >>= 1) {
      unsigned long long o = __shfl_xor_sync(0xffffffffu, m, off);
      m = (o < m) ? o : m;
    }
    if (lane == k) mine = m;
    if (cand == m) {
      p++;
      cand = (p < 8) ? best[p] : 0xFFFFFFFFFFFFFFFFULL;
    }
  }
  return m;
}

__global__ __launch_bounds__(256) void knn_kernel(const float* __restrict__ cg) {
  const int t = (blockIdx.x * 256 + threadIdx.x) >> 5;
  const int lane = threadIdx.x & 31;

  const float gx = cg[t];
  const float gy = cg[T_GRID + t];
  const int hbx = clampb((int)(gx * (float)GBINS));
  const int hby = clampb((int)(gy * (float)GBINS));

  unsigned long long best[8];
#pragma unroll
  for (int i = 0; i < 8; i++) best[i] = 0x7F800000FFFFFFFFULL;
  float worst = __int_as_float(0x7F800000);

  int myCnt = 0, myBase = 0;
  if (lane < 9) {
    const int bx = hbx + (lane % 3) - 1;
    const int by = hby + (lane / 3) - 1;
    if (bx >= 0 && bx < GBINS && by >= 0 && by < GBINS) {
      const int b = bx * GBINS + by;
      myCnt = min(g_cnt[b], BCAP);
      myBase = b * BCAP;
    }
  }

#pragma unroll
  for (int i = 0; i < 9; i++) {
    const int cnt = __shfl_sync(0xffffffffu, myCnt, i);
    const int base = __shfl_sync(0xffffffffu, myBase, i);
    for (int c = lane; c < cnt; c += 32)
      try_candidate(base + c, gx, gy, best, worst);
  }

  unsigned long long mine = 0;
  unsigned long long m8 = merge8_32(best, lane, mine);
  float gw = __uint_as_float((unsigned)(m8 >> 32));

  for (int r = 2; r < GBINS; r++) {
    const float dmin = (float)(r - 1) * CELL;
    if (dmin * dmin > gw) break;
    const int nring = 8 * r;
    for (int idx = lane; idx < nring; idx += 32) {
      const int seg = idx / (2 * r);
      const int off = idx - seg * 2 * r;
      int dx, dy;
      if (seg == 0) { dx = -r + off; dy = -r; }
      else if (seg == 1) { dx = -r + 1 + off; dy = r; }
      else if (seg == 2) { dx = -r; dy = -r + 1 + off; }
      else { dx = r; dy = -r + off; }
      const int bx = hbx + dx, by = hby + dy;
      if (bx < 0 || bx >= GBINS || by < 0 || by >= GBINS) continue;
      const int b = bx * GBINS + by;
      const int cnt = min(g_cnt[b], BCAP);
      const int base = b * BCAP;
      for (int c = 0; c < cnt; c++) try_candidate(base + c, gx, gy, best, worst);
    }
    m8 = merge8_32(best, lane, mine);
    gw = __uint_as_float((unsigned)(m8 >> 32));
  }

  if (lane < 8) g_idx[t * NHBR + lane] = (int)(mine & 0xFFFFFFFFu);
}

// ---------------------------------------------------------------------------
// Weights + xg, j-split 2x (R15 structure): thread = (pt, n, h),
// tid = pt*16 + n*2 + h. Bank-conflict-free tables:
//   sKWt[j*266 + n*33 + d]  (R15, proven -2.1us)
//   sW2p[h*258 + jj*8 + q]  (NEW: h=1 offset 8 banks -> no 2-way on LDS.128)
//   sW1a/sW1b/sB1p[h*33+jj] (NEW: no 2-way on the per-iteration scalar reads)
// Block = 512 threads = 32 points.
// ---------------------------------------------------------------------------
__device__ __forceinline__ void fma4(float4& a, float w, const float4 v) {
  a.x = fmaf(w, v.x, a.x);
  a.y = fmaf(w, v.y, a.y);
  a.z = fmaf(w, v.z, a.z);
  a.w = fmaf(w, v.w, a.w);
}

__global__ __launch_bounds__(512) void weights_xg_kernel(
    const float* __restrict__ x,
    const float* __restrict__ cs, const float* __restrict__ cg,
    const float* __restrict__ w1, const float* __restrict__ b1,
    const float* __restrict__ w2, const float* __restrict__ b2,
    const float* __restrict__ lng, const float* __restrict__ lnb,
    const float* __restrict__ kw, const float* __restrict__ kb) {
  __shared__ float sW1a[66], sW1b[66], sB1p[66];
  __shared__ float4 sW2p[516];     // 2 halves x 256 + pad 2 between
  __shared__ float sKWt[8 * 266];  // [j(266-stride)][n(33-stride)][d]
  __shared__ float sB2[32], sLNG[32], sLNB[32], sKB[8];
  __shared__ int sIDX[256];
  __shared__ float sWgt[256];

  const int tid = threadIdx.x;
  if (tid < 64) {
    const int hh = tid >> 5, jj = tid & 31;
    sW1a[hh * 33 + jj] = w1[tid];        // w1 row 0
    sW1b[hh * 33 + jj] = w1[64 + tid];   // w1 row 1
    sB1p[hh * 33 + jj] = b1[tid];
  }
  {
    const int i = tid;  // 512 float4s of w2
    const int j = i >> 3, q = i & 7;
    sW2p[(j >> 5) * 258 + (j & 31) * 8 + q] = ((const float4*)w2)[i];
  }
  // k_w: src scalar i = row*8 + j (row = n*32 + d) -> sKWt[j*266 + n*33 + d]
  for (int i = tid; i < 2048; i += 512) {
    const int row = i >> 3, j = i & 7;
    sKWt[j * 266 + (row >> 5) * 33 + (row & 31)] = kw[i];
  }
  if (tid < 32) {
    sB2[tid] = b2[tid];
    sLNG[tid] = lng[tid];
    sLNB[tid] = lnb[tid];
  }
  if (tid < 8) sKB[tid] = kb[tid];

  const int pt = tid >> 4;
  const int n = (tid >> 1) & 7;
  const int h = tid & 1;
  const int t = blockIdx.x * 32 + pt;
  const int si = g_idx[t * NHBR + n];
  if (h == 0) sIDX[pt * 8 + n] = si;
  const float r0 = cs[si] - cg[t];
  const float r1 = cs[S_SRC + si] - cg[T_GRID + t];

  __syncthreads();

  float pe[32];
#pragma unroll
  for (int d = 0; d < 32; d++) pe[d] = h ? 0.0f : sB2[d];

  const int hb = h * 33;
  const int hb4 = h * 258;
#pragma unroll 2
  for (int jj = 0; jj < 32; jj++) {
    float hv = fmaf(r1, sW1b[hb + jj], fmaf(r0, sW1a[hb + jj], sB1p[hb + jj]));
    float z = 0.7978845608028654f * fmaf(0.044715f, hv * hv * hv, hv);
    float g = hv * __fdividef(1.0f, 1.0f + __expf(-2.0f * z));  // gelu_tanh
#pragma unroll
    for (int q = 0; q < 8; q++) {
      float4 wv = sW2p[hb4 + jj * 8 + q];
      pe[q * 4 + 0] = fmaf(g, wv.x, pe[q * 4 + 0]);
      pe[q * 4 + 1] = fmaf(g, wv.y, pe[q * 4 + 1]);
      pe[q * 4 + 2] = fmaf(g, wv.z, pe[q * 4 + 2]);
      pe[q * 4 + 3] = fmaf(g, wv.w, pe[q * 4 + 3]);
    }
  }

  // Combine j-halves: partner is lane^1.
#pragma unroll
  for (int d = 0; d < 32; d++)
    pe[d] += __shfl_xor_sync(0xffffffffu, pe[d], 1);

  // LayerNorm (both h compute identically on the combined pe).
  float mu = 0.f;
#pragma unroll
  for (int d = 0; d < 32; d++) mu += pe[d];
  mu *= (1.0f / 32.0f);
  float var = 0.f;
#pragma unroll
  for (int d = 0; d < 32; d++) {
    float c = pe[d] - mu;
    var = fmaf(c, c, var);
  }
  var *= (1.0f / 32.0f);
  const float rstd = rsqrtf(var + 1e-5f);
#pragma unroll
  for (int d = 0; d < 32; d++)
    pe[d] = fmaf((pe[d] - mu) * rstd, sLNG[d], sLNB[d]);  // kf in place

  // Partial logits: this thread covers outputs [h*4, h*4+4). Conflict-free
  // scalar reads from the transposed table.
  float pl[4] = {0.f, 0.f, 0.f, 0.f};
  const float* kt0 = sKWt + (h * 4 + 0) * 266 + n * 33;
  const float* kt1 = kt0 + 266;
  const float* kt2 = kt1 + 266;
  const float* kt3 = kt2 + 266;
#pragma unroll
  for (int d = 0; d < 32; d++) {
    pl[0] = fmaf(pe[d], kt0[d], pl[0]);
    pl[1] = fmaf(pe[d], kt1[d], pl[1]);
    pl[2] = fmaf(pe[d], kt2[d], pl[2]);
    pl[3] = fmaf(pe[d], kt3[d], pl[3]);
  }
  // Reduce over n (tid bits 1..3 -> xor offsets 2,4,8; intra-warp).
#pragma unroll
  for (int k = 0; k < 4; k++) {
    pl[k] += __shfl_xor_sync(0xffffffffu, pl[k], 2);
    pl[k] += __shfl_xor_sync(0xffffffffu, pl[k], 4);
    pl[k] += __shfl_xor_sync(0xffffffffu, pl[k], 8);
  }
  // Fetch the other output half from the h-partner.
  float oth[4];
#pragma unroll
  for (int k = 0; k < 4; k++) oth[k] = __shfl_xor_sync(0xffffffffu, pl[k], 1);

  float lg[8];
#pragma unroll
  for (int k = 0; k < 4; k++) {
    lg[k] = h ? oth[k] : pl[k];
    lg[4 + k] = h ? pl[k] : oth[k];
  }
#pragma unroll
  for (int j = 0; j < 8; j++) lg[j] += sKB[j];

  // Softmax over the 8 outputs, in-register (identical on all 16 pt-threads).
  float mx = lg[0];
#pragma unroll
  for (int j = 1; j < 8; j++) mx = fmaxf(mx, lg[j]);
  float e[8];
  float ssum = 0.f;
#pragma unroll
  for (int j = 0; j < 8; j++) {
    e[j] = __expf(lg[j] - mx);
    ssum += e[j];
  }
  const float inv = __fdividef(1.0f, ssum);
  if (n == 0 && h == 0) {
#pragma unroll
    for (int j = 0; j < 8; j++) sWgt[pt * 8 + j] = e[j] * inv;
  }
  __syncthreads();

  // xg gather: unit = (pt, b); 4 threads per unit, float4 channels each.
  const int u = tid >> 2;
  const int qd = tid & 3;
  const int pt2 = u >> 2;
  const int b = u & 3;
  const int tg = blockIdx.x * 32 + pt2;
  float4 acc = {0, 0, 0, 0};
#pragma unroll
  for (int nn = 0; nn < NHBR; nn++) {
    const int s = sIDX[pt2 * 8 + nn];
    const float w = sWgt[pt2 * 8 + nn];
    const float4 v =
        *(const float4*)(x + (size_t)(b * S_SRC + s) * EDIM + qd * 4);
    fma4(acc, w, v);
  }
  *(float4*)(g_xg + (size_t)((b << 12) + tg) * EDIM + qd * 4) = acc;
}

// ---------------------------------------------------------------------------
// Gaussian axis window, factorized (identical math since R5).
// ---------------------------------------------------------------------------
__device__ __forceinline__ void axis_weights(float pos, float rp,
                                             const float* __restrict__ sC,
                                             float w[5]) {
  const float delta = rp - pos;
  const float lnr = -(20.0f / 89.0f) * delta;
  const float r = __expf(lnr);

  float S0 = 0.f, S1 = 0.f, S2 = 0.f, S3 = 0.f, S4 = 0.f;
  float rr = 1.0f;
#pragma unroll
  for (int k = 0; k < 18; k++) {
    S0 = fmaf(sC[k], rr, S0);
    S1 = fmaf(sC[18 + k], rr, S1);
    S2 = fmaf(sC[36 + k], rr, S2);
    S3 = fmaf(sC[54 + k], rr, S3);
    S4 = fmaf(sC[72 + k], rr, S4);
    rr *= r;
  }
  const float q = rr;
  const float q2 = q * q;
  w[0] = S0;
  w[1] = q * S1;
  w[2] = q2 * S2;
  w[3] = q2 * q * S3;
  w[4] = q2 * q2 * S4;

  const int irp = (int)rp;
  if (irp <= 2 || irp >= 62) {
    const float G = __expf(fmaf(-2.0f * delta, delta, 10.0f * delta));
#pragma unroll
    for (int i = 0; i < 5; i++) w[i] *= G;
    if (irp <= 2) {
      const int j0 = (int)ceilf((2.5f - rp) * 17.8f);
      const float K = __expf(-2.0f * pos * pos);
      float rj = G;
#pragma unroll
      for (int i = 0; i < 5; i++) {
        const int jlo = i * 18;
        const int jhi = min(j0, jlo + 18);
        float c = 0.f;
        for (int j = jlo; j < jhi; j++) {
          c += K - sC[j] * rj;
          rj *= r;
        }
        w[i] += c;
      }
    } else {
      const float d64 = 64.0f - pos;
      const float K = __expf(-2.0f * d64 * d64);
      const int jc = (int)floorf((66.5f - rp) * 17.8f) + 1;
      float rjj = G * __expf(lnr * (float)jc);
#pragma unroll
      for (int i = 0; i < 5; i++) {
        const int jlo = max(jc, i * 18);
        const int jhi = (i + 1) * 18;
        float c = 0.f;
        for (int j = jlo; j < jhi; j++) {
          c += K - sC[j] * rjj;
          rjj *= r;
        }
        w[i] += c;
      }
    }
  }
}

// ---------------------------------------------------------------------------
// Gaussian-window resampling — R7's measured-best shape (9.3us): FOUR threads
// per (b, n); quad&1 selects WHICH axis this thread computes, partner
// exchange via shfl_xor(1); each thread gathers its own float4 of channels.
// Zeroes g_cnt (block 0) for the next graph replay.
// ---------------------------------------------------------------------------
__global__ __launch_bounds__(256, 4) void interp_kernel(
    const float* __restrict__ ct, float* __restrict__ out) {
  __shared__ float sC[90];
  {
    const int tt = threadIdx.x;
    if (tt < 90) {
      float off = fmaf((float)tt, -5.0f / 89.0f, 2.5f);
      sC[tt] = __expf(-2.0f * off * off);
    }
    if (blockIdx.x == 0) {
      for (int i = tt; i < NBINS; i += 256) g_cnt[i] = 0;
    }
  }
  __syncthreads();

  const int gid4 = blockIdx.x * 256 + threadIdx.x;  // 131072 = 4*B*N
  const int tgt = gid4 >> 2;
  const int quad = gid4 & 3;
  const int half = quad & 1;
  const int b = tgt >> 13;
  const float2 c2 = ((const float2*)ct)[tgt];
  const float posx = c2.y * 63.0f;
  const float posy = c2.x * 63.0f;
  const float rpx = rintf(posx);
  const float rpy = rintf(posy);

  const float pos = half ? posy : posx;
  const float rp = half ? rpy : rpx;

  float w[5];
  axis_weights(pos, rp, sC, w);

  float o[5];
#pragma unroll
  for (int i = 0; i < 5; i++) o[i] = __shfl_xor_sync(0xffffffffu, w[i], 1);

  float wx[5], wy[5];
#pragma unroll
  for (int i = 0; i < 5; i++) {
    wx[i] = half ? o[i] : w[i];
    wy[i] = half ? w[i] : o[i];
  }
  const float sx = wx[0] + wx[1] + wx[2] + wx[3] + wx[4];
  const float sy = wy[0] + wy[1] + wy[2] + wy[3] + wy[4];
  const float inv = 1.0f / (sx * sy);

  int ixi[5], iyi[5];
  const int irpx = (int)rpx;
  const int irpy = (int)rpy;
#pragma unroll
  for (int k = 0; k < 5; k++) {
    ixi[k] = min(max(irpx + 2 - k, 0), 63);
    iyi[k] = min(max(irpy + 2 - k, 0), 63);
  }

  float4 acc = {0, 0, 0, 0};
  const float* gbase = g_xg + (size_t)b * (T_GRID * EDIM) + quad * 4;
#pragma unroll
  for (int kx = 0; kx < 5; kx++) {
    const int rowbase = ixi[kx] << 6;
    const float wxk = wx[kx] * inv;
#pragma unroll
    for (int ky = 0; ky < 5; ky++) {
      const float wc = wxk * wy[ky];
      const float4 v =
          *(const float4*)(gbase + (size_t)(rowbase + iyi[ky]) * EDIM);
      fma4(acc, wc, v);
    }
  }
  ((float4*)(out + (size_t)tgt * EDIM))[quad] = acc;
}

// ---------------------------------------------------------------------------
extern "C" void kernel_launch(void* const* d_in, const int* in_sizes, int n_in,
                              void* d_out, int out_size) {
  const float* x   = (const float*)d_in[0];
  const float* cs  = (const float*)d_in[1];
  const float* cg  = (const float*)d_in[2];
  const float* ct  = (const float*)d_in[3];
  const float* w1  = (const float*)d_in[4];
  const float* b1  = (const float*)d_in[5];
  const float* w2  = (const float*)d_in[6];
  const float* b2  = (const float*)d_in[7];
  const float* lng = (const float*)d_in[8];
  const float* lnb = (const float*)d_in[9];
  const float* kw  = (const float*)d_in[10];
  const float* kb  = (const float*)d_in[11];
  float* out = (float*)d_out;

  bins_build<<<64, 256>>>(cs);
  knn_kernel<<<512, 256>>>(cg);
  weights_xg_kernel<<<128, 512>>>(x, cs, cg, w1, b1, w2, b2, lng, lnb, kw, kb);
  interp_kernel<<<512, 256>>>(ct, out);
}

// round 17
// speedup vs baseline: 1.3184x; 1.0065x over previous
#include <cuda_runtime.h>

#define S_SRC 16384
#define T_GRID 4096
#define NHBR 8
#define BATCH 4
#define EDIM 16
#define GBINS 64
#define NBINS (GBINS * GBINS)
#define CELL (1.0f / 64.0f)
#define BCAP 32

// Scratch (static device globals — no allocation). g_cnt zero-initialized at
// load; re-zeroed each launch by interp_kernel block 0 for graph replays.
__device__ float  g_xg[BATCH * T_GRID * EDIM];
__device__ int    g_cnt[NBINS];
__device__ float4 g_bpt[NBINS * BCAP];    // (x, y, idx_bits, 0) packed record
__device__ float4 g_nb[T_GRID * NHBR];    // (r0, r1, idx_bits, 0) per neighbor

__device__ __forceinline__ int clampb(int v) { return min(max(v, 0), GBINS - 1); }

// ---------------------------------------------------------------------------
// Binning: direct scatter into fixed-capacity bins (Poisson(4); BCAP=32
// overflow probability ~4e-9). One packed float4 record per point.
// Bin-internal order nondeterministic, but top-k uses a total order on
// (d2,idx) keys -> deterministic output.
// ---------------------------------------------------------------------------
__global__ __launch_bounds__(256) void bins_build(const float* __restrict__ cs) {
  const int i = blockIdx.x * 256 + threadIdx.x;
  const float x = cs[i];
  const float y = cs[S_SRC + i];
  const int b = clampb((int)(x * (float)GBINS)) * GBINS +
                clampb((int)(y * (float)GBINS));
  const int p = atomicAdd(&g_cnt[b], 1);
  if (p < BCAP) {
    g_bpt[b * BCAP + p] = make_float4(x, y, __int_as_float(i), 0.0f);
  }
}

// ---------------------------------------------------------------------------
// Exact kNN (k=8): ONE WARP per grid point.
// Key = (f32bits(d2)<<32)|idx reproduces lax.top_k(-d2) order + tie-break.
// Packed bin records: one LDG.128 per candidate.
// ---------------------------------------------------------------------------
__device__ __forceinline__ void insert_key(unsigned long long key,
                                           unsigned long long best[8],
                                           float& worst) {
  if (key < best[7]) {
    best[7] = key;
#pragma unroll
    for (int k = 7; k > 0; k--) {
      unsigned long long lo = (best[k] < best[k - 1]) ? best[k] : best[k - 1];
      unsigned long long hi = (best[k] < best[k - 1]) ? best[k - 1] : best[k];
      best[k - 1] = lo;
      best[k] = hi;
    }
    worst = __uint_as_float((unsigned)(best[7] >> 32));
  }
}

__device__ __forceinline__ void try_candidate(int slot, float gx, float gy,
                                              unsigned long long best[8],
                                              float& worst) {
  const float4 p = g_bpt[slot];
  const float dx = gx - p.x;
  const float dy = gy - p.y;
  const float d2 = fmaf(dy, dy, dx * dx);
  if (d2 <= worst) {
    unsigned long long key = ((unsigned long long)__float_as_uint(d2) << 32) |
                             (unsigned)__float_as_int(p.z);
    insert_key(key, best, worst);
  }
}

__device__ __forceinline__ unsigned long long merge8_32(
    const unsigned long long best[8], int lane, unsigned long long& mine) {
  unsigned long long cand = best[0];
  int p = 0;
  unsigned long long m = 0;
#pragma unroll
  for (int k = 0; k < 8; k++) {
    m = cand;
#pragma unroll
    for (int off = 16; off > 0; off >>= 1) {
      unsigned long long o = __shfl_xor_sync(0xffffffffu, m, off);
      m = (o < m) ? o : m;
    }
    if (lane == k) mine = m;
    if (cand == m) {
      p++;
      cand = (p < 8) ? best[p] : 0xFFFFFFFFFFFFFFFFULL;
    }
  }
  return m;
}

__global__ __launch_bounds__(256) void knn_kernel(const float* __restrict__ cg,
                                                  const float* __restrict__ cs) {
  const int t = (blockIdx.x * 256 + threadIdx.x) >> 5;
  const int lane = threadIdx.x & 31;

  const float gx = cg[t];
  const float gy = cg[T_GRID + t];
  const int hbx = clampb((int)(gx * (float)GBINS));
  const int hby = clampb((int)(gy * (float)GBINS));

  unsigned long long best[8];
#pragma unroll
  for (int i = 0; i < 8; i++) best[i] = 0x7F800000FFFFFFFFULL;
  float worst = __int_as_float(0x7F800000);

  int myCnt = 0, myBase = 0;
  if (lane < 9) {
    const int bx = hbx + (lane % 3) - 1;
    const int by = hby + (lane / 3) - 1;
    if (bx >= 0 && bx < GBINS && by >= 0 && by < GBINS) {
      const int b = bx * GBINS + by;
      myCnt = min(g_cnt[b], BCAP);
      myBase = b * BCAP;
    }
  }

#pragma unroll
  for (int i = 0; i < 9; i++) {
    const int cnt = __shfl_sync(0xffffffffu, myCnt, i);
    const int base = __shfl_sync(0xffffffffu, myBase, i);
    for (int c = lane; c < cnt; c += 32)
      try_candidate(base + c, gx, gy, best, worst);
  }

  unsigned long long mine = 0;
  unsigned long long m8 = merge8_32(best, lane, mine);
  float gw = __uint_as_float((unsigned)(m8 >> 32));

  for (int r = 2; r < GBINS; r++) {
    const float dmin = (float)(r - 1) * CELL;
    if (dmin * dmin > gw) break;
    const int nring = 8 * r;
    for (int idx = lane; idx < nring; idx += 32) {
      const int seg = idx / (2 * r);
      const int off = idx - seg * 2 * r;
      int dx, dy;
      if (seg == 0) { dx = -r + off; dy = -r; }
      else if (seg == 1) { dx = -r + 1 + off; dy = r; }
      else if (seg == 2) { dx = -r; dy = -r + 1 + off; }
      else { dx = r; dy = -r + off; }
      const int bx = hbx + dx, by = hby + dy;
      if (bx < 0 || bx >= GBINS || by < 0 || by >= GBINS) continue;
      const int b = bx * GBINS + by;
      const int cnt = min(g_cnt[b], BCAP);
      const int base = b * BCAP;
      for (int c = 0; c < cnt; c++) try_candidate(base + c, gx, gy, best, worst);
    }
    m8 = merge8_32(best, lane, mine);
    gw = __uint_as_float((unsigned)(m8 >> 32));
  }

  // Emit packed neighbor records: rel coords + idx. Saves wx the scattered
  // cs gathers (its entry becomes one coalesced LDG.128).
  if (lane < 8) {
    const int idx = (int)(mine & 0xFFFFFFFFu);
    g_nb[t * NHBR + lane] = make_float4(cs[idx] - gx, cs[S_SRC + idx] - gy,
                                        __int_as_float(idx), 0.0f);
  }
}

// ---------------------------------------------------------------------------
// Weights + xg, j-split 2x (R16 structure): thread = (pt, n, h),
// tid = pt*16 + n*2 + h. Bank-conflict-free tables (R15/R16 proven):
//   sKWt[j*266 + n*33 + d], sW2p[h*258 + jj*8 + q], sW1a/sW1b/sB1p[h*33+jj].
// Entry reads ONE float4 neighbor record instead of idx + 2 scattered cs.
// Block = 512 threads = 32 points.
// ---------------------------------------------------------------------------
__device__ __forceinline__ void fma4(float4& a, float w, const float4 v) {
  a.x = fmaf(w, v.x, a.x);
  a.y = fmaf(w, v.y, a.y);
  a.z = fmaf(w, v.z, a.z);
  a.w = fmaf(w, v.w, a.w);
}

__global__ __launch_bounds__(512) void weights_xg_kernel(
    const float* __restrict__ x,
    const float* __restrict__ w1, const float* __restrict__ b1,
    const float* __restrict__ w2, const float* __restrict__ b2,
    const float* __restrict__ lng, const float* __restrict__ lnb,
    const float* __restrict__ kw, const float* __restrict__ kb) {
  __shared__ float sW1a[66], sW1b[66], sB1p[66];
  __shared__ float4 sW2p[516];     // 2 halves x 256 + pad 2 between
  __shared__ float sKWt[8 * 266];  // [j(266-stride)][n(33-stride)][d]
  __shared__ float sB2[32], sLNG[32], sLNB[32], sKB[8];
  __shared__ int sIDX[256];
  __shared__ float sWgt[256];

  const int tid = threadIdx.x;
  if (tid < 64) {
    const int hh = tid >> 5, jj = tid & 31;
    sW1a[hh * 33 + jj] = w1[tid];
    sW1b[hh * 33 + jj] = w1[64 + tid];
    sB1p[hh * 33 + jj] = b1[tid];
  }
  {
    const int i = tid;
    const int j = i >> 3, q = i & 7;
    sW2p[(j >> 5) * 258 + (j & 31) * 8 + q] = ((const float4*)w2)[i];
  }
  for (int i = tid; i < 2048; i += 512) {
    const int row = i >> 3, j = i & 7;
    sKWt[j * 266 + (row >> 5) * 33 + (row & 31)] = kw[i];
  }
  if (tid < 32) {
    sB2[tid] = b2[tid];
    sLNG[tid] = lng[tid];
    sLNB[tid] = lnb[tid];
  }
  if (tid < 8) sKB[tid] = kb[tid];

  const int pt = tid >> 4;
  const int n = (tid >> 1) & 7;
  const int h = tid & 1;
  const int t = blockIdx.x * 32 + pt;
  const float4 nb = g_nb[t * NHBR + n];  // both h threads: broadcast
  const float r0 = nb.x;
  const float r1 = nb.y;
  if (h == 0) sIDX[pt * 8 + n] = __float_as_int(nb.z);

  __syncthreads();

  float pe[32];
#pragma unroll
  for (int d = 0; d < 32; d++) pe[d] = h ? 0.0f : sB2[d];

  const int hb = h * 33;
  const int hb4 = h * 258;
#pragma unroll 2
  for (int jj = 0; jj < 32; jj++) {
    float hv = fmaf(r1, sW1b[hb + jj], fmaf(r0, sW1a[hb + jj], sB1p[hb + jj]));
    float z = 0.7978845608028654f * fmaf(0.044715f, hv * hv * hv, hv);
    float g = hv * __fdividef(1.0f, 1.0f + __expf(-2.0f * z));  // gelu_tanh
#pragma unroll
    for (int q = 0; q < 8; q++) {
      float4 wv = sW2p[hb4 + jj * 8 + q];
      pe[q * 4 + 0] = fmaf(g, wv.x, pe[q * 4 + 0]);
      pe[q * 4 + 1] = fmaf(g, wv.y, pe[q * 4 + 1]);
      pe[q * 4 + 2] = fmaf(g, wv.z, pe[q * 4 + 2]);
      pe[q * 4 + 3] = fmaf(g, wv.w, pe[q * 4 + 3]);
    }
  }

#pragma unroll
  for (int d = 0; d < 32; d++)
    pe[d] += __shfl_xor_sync(0xffffffffu, pe[d], 1);

  float mu = 0.f;
#pragma unroll
  for (int d = 0; d < 32; d++) mu += pe[d];
  mu *= (1.0f / 32.0f);
  float var = 0.f;
#pragma unroll
  for (int d = 0; d < 32; d++) {
    float c = pe[d] - mu;
    var = fmaf(c, c, var);
  }
  var *= (1.0f / 32.0f);
  const float rstd = rsqrtf(var + 1e-5f);
#pragma unroll
  for (int d = 0; d < 32; d++)
    pe[d] = fmaf((pe[d] - mu) * rstd, sLNG[d], sLNB[d]);

  float pl[4] = {0.f, 0.f, 0.f, 0.f};
  const float* kt0 = sKWt + (h * 4 + 0) * 266 + n * 33;
  const float* kt1 = kt0 + 266;
  const float* kt2 = kt1 + 266;
  const float* kt3 = kt2 + 266;
#pragma unroll
  for (int d = 0; d < 32; d++) {
    pl[0] = fmaf(pe[d], kt0[d], pl[0]);
    pl[1] = fmaf(pe[d], kt1[d], pl[1]);
    pl[2] = fmaf(pe[d], kt2[d], pl[2]);
    pl[3] = fmaf(pe[d], kt3[d], pl[3]);
  }
#pragma unroll
  for (int k = 0; k < 4; k++) {
    pl[k] += __shfl_xor_sync(0xffffffffu, pl[k], 2);
    pl[k] += __shfl_xor_sync(0xffffffffu, pl[k], 4);
    pl[k] += __shfl_xor_sync(0xffffffffu, pl[k], 8);
  }
  float oth[4];
#pragma unroll
  for (int k = 0; k < 4; k++) oth[k] = __shfl_xor_sync(0xffffffffu, pl[k], 1);

  float lg[8];
#pragma unroll
  for (int k = 0; k < 4; k++) {
    lg[k] = h ? oth[k] : pl[k];
    lg[4 + k] = h ? pl[k] : oth[k];
  }
#pragma unroll
  for (int j = 0; j < 8; j++) lg[j] += sKB[j];

  float mx = lg[0];
#pragma unroll
  for (int j = 1; j < 8; j++) mx = fmaxf(mx, lg[j]);
  float e[8];
  float ssum = 0.f;
#pragma unroll
  for (int j = 0; j < 8; j++) {
    e[j] = __expf(lg[j] - mx);
    ssum += e[j];
  }
  const float inv = __fdividef(1.0f, ssum);
  if (n == 0 && h == 0) {
#pragma unroll
    for (int j = 0; j < 8; j++) sWgt[pt * 8 + j] = e[j] * inv;
  }
  __syncthreads();

  // xg gather: unit = (pt, b); 4 threads per unit, float4 channels each.
  const int u = tid >> 2;
  const int qd = tid & 3;
  const int pt2 = u >> 2;
  const int b = u & 3;
  const int tg = blockIdx.x * 32 + pt2;
  float4 acc = {0, 0, 0, 0};
#pragma unroll
  for (int nn = 0; nn < NHBR; nn++) {
    const int s = sIDX[pt2 * 8 + nn];
    const float w = sWgt[pt2 * 8 + nn];
    const float4 v =
        *(const float4*)(x + (size_t)(b * S_SRC + s) * EDIM + qd * 4);
    fma4(acc, w, v);
  }
  *(float4*)(g_xg + (size_t)((b << 12) + tg) * EDIM + qd * 4) = acc;
}

// ---------------------------------------------------------------------------
// Gaussian axis window, factorized (identical math since R5).
// ---------------------------------------------------------------------------
__device__ __forceinline__ void axis_weights(float pos, float rp,
                                             const float* __restrict__ sC,
                                             float w[5]) {
  const float delta = rp - pos;
  const float lnr = -(20.0f / 89.0f) * delta;
  const float r = __expf(lnr);

  float S0 = 0.f, S1 = 0.f, S2 = 0.f, S3 = 0.f, S4 = 0.f;
  float rr = 1.0f;
#pragma unroll
  for (int k = 0; k < 18; k++) {
    S0 = fmaf(sC[k], rr, S0);
    S1 = fmaf(sC[18 + k], rr, S1);
    S2 = fmaf(sC[36 + k], rr, S2);
    S3 = fmaf(sC[54 + k], rr, S3);
    S4 = fmaf(sC[72 + k], rr, S4);
    rr *= r;
  }
  const float q = rr;
  const float q2 = q * q;
  w[0] = S0;
  w[1] = q * S1;
  w[2] = q2 * S2;
  w[3] = q2 * q * S3;
  w[4] = q2 * q2 * S4;

  const int irp = (int)rp;
  if (irp <= 2 || irp >= 62) {
    const float G = __expf(fmaf(-2.0f * delta, delta, 10.0f * delta));
#pragma unroll
    for (int i = 0; i < 5; i++) w[i] *= G;
    if (irp <= 2) {
      const int j0 = (int)ceilf((2.5f - rp) * 17.8f);
      const float K = __expf(-2.0f * pos * pos);
      float rj = G;
#pragma unroll
      for (int i = 0; i < 5; i++) {
        const int jlo = i * 18;
        const int jhi = min(j0, jlo + 18);
        float c = 0.f;
        for (int j = jlo; j < jhi; j++) {
          c += K - sC[j] * rj;
          rj *= r;
        }
        w[i] += c;
      }
    } else {
      const float d64 = 64.0f - pos;
      const float K = __expf(-2.0f * d64 * d64);
      const int jc = (int)floorf((66.5f - rp) * 17.8f) + 1;
      float rjj = G * __expf(lnr * (float)jc);
#pragma unroll
      for (int i = 0; i < 5; i++) {
        const int jlo = max(jc, i * 18);
        const int jhi = (i + 1) * 18;
        float c = 0.f;
        for (int j = jlo; j < jhi; j++) {
          c += K - sC[j] * rjj;
          rjj *= r;
        }
        w[i] += c;
      }
    }
  }
}

// ---------------------------------------------------------------------------
// Gaussian-window resampling — R7/R16 measured-best shape: FOUR threads per
// (b, n); quad&1 selects WHICH axis this thread computes, partner exchange
// via shfl_xor(1); each thread gathers its own float4 of channels.
// Zeroes g_cnt (block 0) for the next graph replay.
// ---------------------------------------------------------------------------
__global__ __launch_bounds__(256, 4) void interp_kernel(
    const float* __restrict__ ct, float* __restrict__ out) {
  __shared__ float sC[90];
  {
    const int tt = threadIdx.x;
    if (tt < 90) {
      float off = fmaf((float)tt, -5.0f / 89.0f, 2.5f);
      sC[tt] = __expf(-2.0f * off * off);
    }
    if (blockIdx.x == 0) {
      for (int i = tt; i < NBINS; i += 256) g_cnt[i] = 0;
    }
  }
  __syncthreads();

  const int gid4 = blockIdx.x * 256 + threadIdx.x;  // 131072 = 4*B*N
  const int tgt = gid4 >> 2;
  const int quad = gid4 & 3;
  const int half = quad & 1;
  const int b = tgt >> 13;
  const float2 c2 = ((const float2*)ct)[tgt];
  const float posx = c2.y * 63.0f;
  const float posy = c2.x * 63.0f;
  const float rpx = rintf(posx);
  const float rpy = rintf(posy);

  const float pos = half ? posy : posx;
  const float rp = half ? rpy : rpx;

  float w[5];
  axis_weights(pos, rp, sC, w);

  float o[5];
#pragma unroll
  for (int i = 0; i < 5; i++) o[i] = __shfl_xor_sync(0xffffffffu, w[i], 1);

  float wx[5], wy[5];
#pragma unroll
  for (int i = 0; i < 5; i++) {
    wx[i] = half ? o[i] : w[i];
    wy[i] = half ? w[i] : o[i];
  }
  const float sx = wx[0] + wx[1] + wx[2] + wx[3] + wx[4];
  const float sy = wy[0] + wy[1] + wy[2] + wy[3] + wy[4];
  const float inv = 1.0f / (sx * sy);

  int ixi[5], iyi[5];
  const int irpx = (int)rpx;
  const int irpy = (int)rpy;
#pragma unroll
  for (int k = 0; k < 5; k++) {
    ixi[k] = min(max(irpx + 2 - k, 0), 63);
    iyi[k] = min(max(irpy + 2 - k, 0), 63);
  }

  float4 acc = {0, 0, 0, 0};
  const float* gbase = g_xg + (size_t)b * (T_GRID * EDIM) + quad * 4;
#pragma unroll
  for (int kx = 0; kx < 5; kx++) {
    const int rowbase = ixi[kx] << 6;
    const float wxk = wx[kx] * inv;
#pragma unroll
    for (int ky = 0; ky < 5; ky++) {
      const float wc = wxk * wy[ky];
      const float4 v =
          *(const float4*)(gbase + (size_t)(rowbase + iyi[ky]) * EDIM);
      fma4(acc, wc, v);
    }
  }
  ((float4*)(out + (size_t)tgt * EDIM))[quad] = acc;
}

// ---------------------------------------------------------------------------
extern "C" void kernel_launch(void* const* d_in, const int* in_sizes, int n_in,
                              void* d_out, int out_size) {
  const float* x   = (const float*)d_in[0];
  const float* cs  = (const float*)d_in[1];
  const float* cg  = (const float*)d_in[2];
  const float* ct  = (const float*)d_in[3];
  const float* w1  = (const float*)d_in[4];
  const float* b1  = (const float*)d_in[5];
  const float* w2  = (const float*)d_in[6];
  const float* b2  = (const float*)d_in[7];
  const float* lng = (const float*)d_in[8];
  const float* lnb = (const float*)d_in[9];
  const float* kw  = (const float*)d_in[10];
  const float* kb  = (const float*)d_in[11];
  float* out = (float*)d_out;

  bins_build<<<64, 256>>>(cs);
  knn_kernel<<<512, 256>>>(cg, cs);
  weights_xg_kernel<<<128, 512>>>(x, w1, b1, w2, b2, lng, lnb, kw, kb);
  interp_kernel<<<512, 256>>>(ct, out);
}